// round 4
// baseline (speedup 1.0000x reference)
#include <cuda_runtime.h>
#include <cuda_bf16.h>

#define NN 100000
#define H  32

// ---------------- scratch (device globals; no allocation allowed) ----------
__device__ __align__(16) float g_h   [NN * H];
__device__ __align__(16) float g_p   [NN * H];
__device__ __align__(16) float g_q   [NN * H];
__device__ __align__(16) float g_aggH[NN * H];
__device__ int   g_cnt[NN];
__device__ int   g_is64;   // 1 if edges are int64 pairs, 0 if int32 pairs

// cooperative copy global -> shared
__device__ __forceinline__ void stage(float* __restrict__ s,
                                      const float* __restrict__ g, int count) {
    for (int i = threadIdx.x; i < count; i += blockDim.x) s[i] = g[i];
}

// fetch src/dst of edge e under either layout
__device__ __forceinline__ void load_edge(const int* __restrict__ ew, int e, int is64,
                                          int& src, int& dst) {
    if (is64) {            // [s0,0,d0,0, s1,0,d1,0, ...]
        src = ew[4 * e];
        dst = ew[4 * e + 2];
    } else {               // [s0,d0, s1,d1, ...]
        src = ew[2 * e];
        dst = ew[2 * e + 1];
    }
}

// x[IN] @ W[IN,H] + b -> out[H], optional relu. W/b in shared memory.
template <int IN, bool RELU>
__device__ __forceinline__ void mlp_layer(const float* __restrict__ x,
                                          float* __restrict__ out,
                                          const float* __restrict__ W,
                                          const float* __restrict__ b) {
#pragma unroll
    for (int k = 0; k < H; k++) {
        float s = b[k];
#pragma unroll
        for (int i = 0; i < IN; i++) s = fmaf(x[i], W[i * H + k], s);
        out[k] = RELU ? fmaxf(s, 0.0f) : s;
    }
}

// ---------------- kernels ----------------------------------------------------

// Detect edge dtype: int64 pairs have all-zero odd words (high halves of
// non-negative node ids); int32 pairs have dst ids there (nonzero w.h.p.).
__global__ void probe_kernel(const int* __restrict__ ew) {
    if (threadIdx.x == 0) {
        int allzero = 1;
        for (int i = 1; i < 64; i += 2)
            if (ew[i] != 0) { allzero = 0; break; }
        g_is64 = allzero;
    }
}

// h = MLP(node_features); also zero per-node edge counts.
__global__ void enc_kernel(const float* __restrict__ nf,
                           const float* __restrict__ w1, const float* __restrict__ b1,
                           const float* __restrict__ w2, const float* __restrict__ b2,
                           int n) {
    __shared__ float sW1[16 * H], sB1[H], sW2[H * H], sB2[H];
    stage(sW1, w1, 16 * H);
    stage(sB1, b1, H);
    stage(sW2, w2, H * H);
    stage(sB2, b2, H);
    __syncthreads();

    int v = blockIdx.x * blockDim.x + threadIdx.x;
    if (v >= n) return;
    float x[16];
    const float4* nr = (const float4*)(nf + (size_t)v * 16);
#pragma unroll
    for (int j = 0; j < 4; j++) {
        float4 t = nr[j];
        x[4 * j + 0] = t.x; x[4 * j + 1] = t.y; x[4 * j + 2] = t.z; x[4 * j + 3] = t.w;
    }
    float t1[H];
    mlp_layer<16, true>(x, t1, sW1, sB1);
    float t2[H];
    mlp_layer<H, false>(t1, t2, sW2, sB2);
    float4* hr = (float4*)(g_h + (size_t)v * H);
#pragma unroll
    for (int j = 0; j < 8; j++)
        hr[j] = make_float4(t2[4 * j], t2[4 * j + 1], t2[4 * j + 2], t2[4 * j + 3]);
    g_cnt[v] = 0;
}

// per-node in-degree (needed to fold b2 through segment_sum)
__global__ void count_kernel(const int* __restrict__ ew, int ne) {
    __shared__ int sIs64;
    if (threadIdx.x == 0) sIs64 = g_is64;
    __syncthreads();
    int e = blockIdx.x * blockDim.x + threadIdx.x;
    if (e >= ne) return;
    int src, dst;
    load_edge(ew, e, sIs64, src, dst);
    atomicAdd(&g_cnt[dst], 1);
}

// p = h @ W1[0:32], q = h @ W1[32:64]; zero aggH row.
__global__ void pq_kernel(const float* __restrict__ msgW1, int r, int n) {
    __shared__ float sW[64 * H];
    stage(sW, msgW1 + r * 68 * H, 64 * H);
    __syncthreads();

    int v = blockIdx.x * blockDim.x + threadIdx.x;
    if (v >= n) return;
    float x[H];
    const float4* hr = (const float4*)(g_h + (size_t)v * H);
#pragma unroll
    for (int j = 0; j < 8; j++) {
        float4 t = hr[j];
        x[4 * j + 0] = t.x; x[4 * j + 1] = t.y; x[4 * j + 2] = t.z; x[4 * j + 3] = t.w;
    }
    float4* pr = (float4*)(g_p + (size_t)v * H);
    float4* qr = (float4*)(g_q + (size_t)v * H);
    float o[H];
#pragma unroll
    for (int k = 0; k < H; k++) {
        float s = 0.0f;
#pragma unroll
        for (int i = 0; i < H; i++) s = fmaf(x[i], sW[i * H + k], s);
        o[k] = s;
    }
#pragma unroll
    for (int j = 0; j < 8; j++)
        pr[j] = make_float4(o[4 * j], o[4 * j + 1], o[4 * j + 2], o[4 * j + 3]);
#pragma unroll
    for (int k = 0; k < H; k++) {
        float s = 0.0f;
#pragma unroll
        for (int i = 0; i < H; i++) s = fmaf(x[i], sW[(32 + i) * H + k], s);
        o[k] = s;
    }
#pragma unroll
    for (int j = 0; j < 8; j++)
        qr[j] = make_float4(o[4 * j], o[4 * j + 1], o[4 * j + 2], o[4 * j + 3]);

    float4 z = make_float4(0.f, 0.f, 0.f, 0.f);
    float4* ar = (float4*)(g_aggH + (size_t)v * H);
#pragma unroll
    for (int j = 0; j < 8; j++) ar[j] = z;
}

// Per edge: hidden = relu(p[src] + q[dst] + ef@W1c + b1); aggH[dst] += hidden.
__global__ void edge_kernel(const int* __restrict__ ew,
                            const float4* __restrict__ ef,
                            const float* __restrict__ msgW1,
                            const float* __restrict__ msgB1,
                            int r, int ne) {
    __shared__ float sWc[4 * H], sB1[H];
    __shared__ int sIs64;
    stage(sWc, msgW1 + r * 68 * H + 64 * H, 4 * H);
    stage(sB1, msgB1 + r * H, H);
    if (threadIdx.x == 0) sIs64 = g_is64;
    __syncthreads();

    int e = blockIdx.x * blockDim.x + threadIdx.x;
    if (e >= ne) return;
    int src, dst;
    load_edge(ew, e, sIs64, src, dst);
    float4 f = ef[e];
    const float4* pr = (const float4*)(g_p + (size_t)src * H);
    const float4* qr = (const float4*)(g_q + (size_t)dst * H);
    float* outp = g_aggH + (size_t)dst * H;
#pragma unroll
    for (int j = 0; j < 8; j++) {
        float4 a = pr[j];
        float4 b = qr[j];
        float sum[4] = {a.x + b.x, a.y + b.y, a.z + b.z, a.w + b.w};
#pragma unroll
        for (int c = 0; c < 4; c++) {
            int k = 4 * j + c;
            float s = sum[c] + sB1[k];
            s = fmaf(f.x, sWc[0 * H + k], s);
            s = fmaf(f.y, sWc[1 * H + k], s);
            s = fmaf(f.z, sWc[2 * H + k], s);
            s = fmaf(f.w, sWc[3 * H + k], s);
            atomicAdd(outp + k, fmaxf(s, 0.0f));
        }
    }
}

// agg = aggH@W2 + cnt*b2 ; h += MLP(concat(h, agg))
__global__ void upd_kernel(const float* __restrict__ msgW2, const float* __restrict__ msgB2,
                           const float* __restrict__ updW1, const float* __restrict__ updB1,
                           const float* __restrict__ updW2, const float* __restrict__ updB2,
                           int r, int n) {
    __shared__ float sW2[H * H], sB2[H];
    __shared__ float sU1[64 * H], sUB1[H], sU2[H * H], sUB2[H];
    stage(sW2, msgW2 + r * H * H, H * H);
    stage(sB2, msgB2 + r * H, H);
    stage(sU1, updW1 + r * 64 * H, 64 * H);
    stage(sUB1, updB1 + r * H, H);
    stage(sU2, updW2 + r * H * H, H * H);
    stage(sUB2, updB2 + r * H, H);
    __syncthreads();

    int v = blockIdx.x * blockDim.x + threadIdx.x;
    if (v >= n) return;
    float h[H], a[H];
    const float4* hr = (const float4*)(g_h + (size_t)v * H);
    const float4* ar = (const float4*)(g_aggH + (size_t)v * H);
#pragma unroll
    for (int j = 0; j < 8; j++) {
        float4 t = hr[j];
        h[4 * j + 0] = t.x; h[4 * j + 1] = t.y; h[4 * j + 2] = t.z; h[4 * j + 3] = t.w;
        float4 u = ar[j];
        a[4 * j + 0] = u.x; a[4 * j + 1] = u.y; a[4 * j + 2] = u.z; a[4 * j + 3] = u.w;
    }
    float fc = (float)g_cnt[v];
    float agg[H];
#pragma unroll
    for (int k = 0; k < H; k++) {
        float s = fc * sB2[k];
#pragma unroll
        for (int i = 0; i < H; i++) s = fmaf(a[i], sW2[i * H + k], s);
        agg[k] = s;
    }
    float t[H];
#pragma unroll
    for (int k = 0; k < H; k++) {
        float s = sUB1[k];
#pragma unroll
        for (int i = 0; i < H; i++) s = fmaf(h[i], sU1[i * H + k], s);
#pragma unroll
        for (int i = 0; i < H; i++) s = fmaf(agg[i], sU1[(32 + i) * H + k], s);
        t[k] = fmaxf(s, 0.0f);
    }
    float o[H];
#pragma unroll
    for (int k = 0; k < H; k++) {
        float s = sUB2[k];
#pragma unroll
        for (int i = 0; i < H; i++) s = fmaf(t[i], sU2[i * H + k], s);
        o[k] = h[k] + s;
    }
    float4* hw = (float4*)(g_h + (size_t)v * H);
#pragma unroll
    for (int j = 0; j < 8; j++)
        hw[j] = make_float4(o[4 * j], o[4 * j + 1], o[4 * j + 2], o[4 * j + 3]);
}

// out = MLP(h)[:,0]
__global__ void head_kernel(float* __restrict__ out,
                            const float* __restrict__ w1, const float* __restrict__ b1,
                            const float* __restrict__ w2, const float* __restrict__ b2,
                            int n) {
    __shared__ float sW1[H * H], sB1[H], sW2[H], sB2[1];
    stage(sW1, w1, H * H);
    stage(sB1, b1, H);
    stage(sW2, w2, H);
    stage(sB2, b2, 1);
    __syncthreads();

    int v = blockIdx.x * blockDim.x + threadIdx.x;
    if (v >= n) return;
    float h[H];
    const float4* hr = (const float4*)(g_h + (size_t)v * H);
#pragma unroll
    for (int j = 0; j < 8; j++) {
        float4 t = hr[j];
        h[4 * j + 0] = t.x; h[4 * j + 1] = t.y; h[4 * j + 2] = t.z; h[4 * j + 3] = t.w;
    }
    float t1[H];
    mlp_layer<H, true>(h, t1, sW1, sB1);
    float s = sB2[0];
#pragma unroll
    for (int k = 0; k < H; k++) s = fmaf(t1[k], sW2[k], s);
    out[v] = s;
}

// ---------------- launch ----------------------------------------------------
extern "C" void kernel_launch(void* const* d_in, const int* in_sizes, int n_in,
                              void* d_out, int out_size) {
    const float* nf    = (const float*)d_in[0];
    const int*   ew    = (const int*)d_in[1];     // edges, layout auto-detected
    const float4* ef   = (const float4*)d_in[2];
    const float* encW1 = (const float*)d_in[3];
    const float* encB1 = (const float*)d_in[4];
    const float* encW2 = (const float*)d_in[5];
    const float* encB2 = (const float*)d_in[6];
    const float* msgW1 = (const float*)d_in[7];
    const float* msgB1 = (const float*)d_in[8];
    const float* msgW2 = (const float*)d_in[9];
    const float* msgB2 = (const float*)d_in[10];
    const float* updW1 = (const float*)d_in[11];
    const float* updB1 = (const float*)d_in[12];
    const float* updW2 = (const float*)d_in[13];
    const float* updB2 = (const float*)d_in[14];
    const float* headW1 = (const float*)d_in[15];
    const float* headB1 = (const float*)d_in[16];
    const float* headW2 = (const float*)d_in[17];
    const float* headB2 = (const float*)d_in[18];

    int n  = in_sizes[0] / 16;  // nodes
    int ne = in_sizes[1] / 2;   // edges (element count / 2, same for i32/i64)

    const int NB = 128;
    int gn = (n + NB - 1) / NB;
    const int EB = 256;
    int ge = (ne + EB - 1) / EB;

    probe_kernel<<<1, 32>>>(ew);
    enc_kernel<<<gn, NB>>>(nf, encW1, encB1, encW2, encB2, n);
    count_kernel<<<ge, EB>>>(ew, ne);
    for (int r = 0; r < 2; r++) {
        pq_kernel<<<gn, NB>>>(msgW1, r, n);
        edge_kernel<<<ge, EB>>>(ew, ef, msgW1, msgB1, r, ne);
        upd_kernel<<<gn, NB>>>(msgW2, msgB2, updW1, updB1, updW2, updB2, r, n);
    }
    head_kernel<<<gn, NB>>>((float*)d_out, headW1, headB1, headW2, headB2, n);
}

// round 5
// speedup vs baseline: 2.2862x; 2.2862x over previous
#include <cuda_runtime.h>
#include <cuda_bf16.h>

#define NN 100000
#define NEMAX 3200000
#define H  32

// ---------------- scratch (device globals; no allocation allowed) ----------
__device__ __align__(16) float g_h   [NN * H];
__device__ __align__(16) float g_p   [NN * H];
__device__ __align__(16) float g_q   [NN * H];
__device__ __align__(16) float g_aggH[NN * H];
__device__ int    g_cnt [NN];
__device__ int    g_off [NN + 1];
__device__ int    g_fill[NN];
__device__ int    g_csrc[NEMAX];                 // src ids in dst-sorted order
__device__ __align__(16) float g_cef[NEMAX * 4]; // edge features, dst-sorted
__device__ int    g_is64;

// cooperative copy global -> shared
__device__ __forceinline__ void stage(float* __restrict__ s,
                                      const float* __restrict__ g, int count) {
    for (int i = threadIdx.x; i < count; i += blockDim.x) s[i] = g[i];
}

__device__ __forceinline__ void load_edge(const int* __restrict__ ew, int e, int is64,
                                          int& src, int& dst) {
    if (is64) { src = ew[4 * e]; dst = ew[4 * e + 2]; }
    else      { src = ew[2 * e]; dst = ew[2 * e + 1]; }
}

template <int IN, bool RELU>
__device__ __forceinline__ void mlp_layer(const float* __restrict__ x,
                                          float* __restrict__ out,
                                          const float* __restrict__ W,
                                          const float* __restrict__ b) {
#pragma unroll
    for (int k = 0; k < H; k++) {
        float s = b[k];
#pragma unroll
        for (int i = 0; i < IN; i++) s = fmaf(x[i], W[i * H + k], s);
        out[k] = RELU ? fmaxf(s, 0.0f) : s;
    }
}

// ---------------- kernels ----------------------------------------------------

__global__ void probe_kernel(const int* __restrict__ ew) {
    if (threadIdx.x == 0) {
        int allzero = 1;
        for (int i = 1; i < 64; i += 2)
            if (ew[i] != 0) { allzero = 0; break; }
        g_is64 = allzero;
    }
}

// h = MLP(node_features); also zero per-node edge counts.
__global__ void enc_kernel(const float* __restrict__ nf,
                           const float* __restrict__ w1, const float* __restrict__ b1,
                           const float* __restrict__ w2, const float* __restrict__ b2,
                           int n) {
    __shared__ float sW1[16 * H], sB1[H], sW2[H * H], sB2[H];
    stage(sW1, w1, 16 * H);
    stage(sB1, b1, H);
    stage(sW2, w2, H * H);
    stage(sB2, b2, H);
    __syncthreads();

    int v = blockIdx.x * blockDim.x + threadIdx.x;
    if (v >= n) return;
    float x[16];
    const float4* nr = (const float4*)(nf + (size_t)v * 16);
#pragma unroll
    for (int j = 0; j < 4; j++) {
        float4 t = nr[j];
        x[4 * j + 0] = t.x; x[4 * j + 1] = t.y; x[4 * j + 2] = t.z; x[4 * j + 3] = t.w;
    }
    float t1[H];
    mlp_layer<16, true>(x, t1, sW1, sB1);
    float t2[H];
    mlp_layer<H, false>(t1, t2, sW2, sB2);
    float4* hr = (float4*)(g_h + (size_t)v * H);
#pragma unroll
    for (int j = 0; j < 8; j++)
        hr[j] = make_float4(t2[4 * j], t2[4 * j + 1], t2[4 * j + 2], t2[4 * j + 3]);
    g_cnt[v] = 0;
}

__global__ void count_kernel(const int* __restrict__ ew, int ne) {
    __shared__ int sIs64;
    if (threadIdx.x == 0) sIs64 = g_is64;
    __syncthreads();
    int e = blockIdx.x * blockDim.x + threadIdx.x;
    if (e >= ne) return;
    int src, dst;
    load_edge(ew, e, sIs64, src, dst);
    atomicAdd(&g_cnt[dst], 1);
}

// exclusive prefix sum of g_cnt -> g_off / g_fill. One block, 1024 threads.
__global__ void scan_kernel(int n) {
    __shared__ int part[1024];
    const int T = 1024;
    int t = threadIdx.x;
    int chunk = (n + T - 1) / T;
    int base = t * chunk;
    int s = 0;
    for (int i = 0; i < chunk; i++) {
        int idx = base + i;
        if (idx < n) s += g_cnt[idx];
    }
    part[t] = s;
    __syncthreads();
    // Hillis-Steele inclusive scan
    for (int o = 1; o < T; o <<= 1) {
        int v = (t >= o) ? part[t - o] : 0;
        __syncthreads();
        part[t] += v;
        __syncthreads();
    }
    int run = (t > 0) ? part[t - 1] : 0;
    for (int i = 0; i < chunk; i++) {
        int idx = base + i;
        if (idx < n) {
            g_off[idx] = run;
            g_fill[idx] = run;
            run += g_cnt[idx];
        }
    }
    if (t == T - 1) g_off[n] = part[T - 1];
}

// scatter edges into dst-sorted CSR: src id + permuted edge features
__global__ void scatter_kernel(const int* __restrict__ ew,
                               const float4* __restrict__ ef, int ne) {
    __shared__ int sIs64;
    if (threadIdx.x == 0) sIs64 = g_is64;
    __syncthreads();
    int e = blockIdx.x * blockDim.x + threadIdx.x;
    if (e >= ne) return;
    int src, dst;
    load_edge(ew, e, sIs64, src, dst);
    int slot = atomicAdd(&g_fill[dst], 1);
    g_csrc[slot] = src;
    ((float4*)g_cef)[slot] = ef[e];
}

// p = h @ W1[0:32], q = h @ W1[32:64].
__global__ void pq_kernel(const float* __restrict__ msgW1, int r, int n) {
    __shared__ float sW[64 * H];
    stage(sW, msgW1 + r * 68 * H, 64 * H);
    __syncthreads();

    int v = blockIdx.x * blockDim.x + threadIdx.x;
    if (v >= n) return;
    float x[H];
    const float4* hr = (const float4*)(g_h + (size_t)v * H);
#pragma unroll
    for (int j = 0; j < 8; j++) {
        float4 t = hr[j];
        x[4 * j + 0] = t.x; x[4 * j + 1] = t.y; x[4 * j + 2] = t.z; x[4 * j + 3] = t.w;
    }
    float4* pr = (float4*)(g_p + (size_t)v * H);
    float4* qr = (float4*)(g_q + (size_t)v * H);
    float o[H];
#pragma unroll
    for (int k = 0; k < H; k++) {
        float s = 0.0f;
#pragma unroll
        for (int i = 0; i < H; i++) s = fmaf(x[i], sW[i * H + k], s);
        o[k] = s;
    }
#pragma unroll
    for (int j = 0; j < 8; j++)
        pr[j] = make_float4(o[4 * j], o[4 * j + 1], o[4 * j + 2], o[4 * j + 3]);
#pragma unroll
    for (int k = 0; k < H; k++) {
        float s = 0.0f;
#pragma unroll
        for (int i = 0; i < H; i++) s = fmaf(x[i], sW[(32 + i) * H + k], s);
        o[k] = s;
    }
#pragma unroll
    for (int j = 0; j < 8; j++)
        qr[j] = make_float4(o[4 * j], o[4 * j + 1], o[4 * j + 2], o[4 * j + 3]);
}

// One warp per dst node, one channel per lane. No atomics.
// aggH[v][k] = sum_e relu(p[src_e][k] + q[v][k] + ef_e @ Wc[:,k] + b1[k])
__global__ void gather_kernel(const float* __restrict__ msgW1,
                              const float* __restrict__ msgB1,
                              int r, int n) {
    int warp = (blockIdx.x * blockDim.x + threadIdx.x) >> 5;
    int k = threadIdx.x & 31;
    if (warp >= n) return;
    int v = warp;

    const float* Wc = msgW1 + r * 68 * H + 64 * H;
    float w0 = Wc[0 * H + k];
    float w1 = Wc[1 * H + k];
    float w2 = Wc[2 * H + k];
    float w3 = Wc[3 * H + k];
    float base = msgB1[r * H + k] + g_q[(size_t)v * H + k];

    int i0 = g_off[v];
    int i1 = g_off[v + 1];
    float acc = 0.0f;
    int i = i0;
    for (; i + 1 < i1; i += 2) {
        int s0 = g_csrc[i];
        int s1 = g_csrc[i + 1];
        float4 f0 = ((const float4*)g_cef)[i];
        float4 f1 = ((const float4*)g_cef)[i + 1];
        float pv0 = g_p[(size_t)s0 * H + k];
        float pv1 = g_p[(size_t)s1 * H + k];
        float a = pv0 + base;
        a = fmaf(f0.x, w0, a); a = fmaf(f0.y, w1, a);
        a = fmaf(f0.z, w2, a); a = fmaf(f0.w, w3, a);
        acc += fmaxf(a, 0.0f);
        float b = pv1 + base;
        b = fmaf(f1.x, w0, b); b = fmaf(f1.y, w1, b);
        b = fmaf(f1.z, w2, b); b = fmaf(f1.w, w3, b);
        acc += fmaxf(b, 0.0f);
    }
    if (i < i1) {
        int s0 = g_csrc[i];
        float4 f0 = ((const float4*)g_cef)[i];
        float pv0 = g_p[(size_t)s0 * H + k];
        float a = pv0 + base;
        a = fmaf(f0.x, w0, a); a = fmaf(f0.y, w1, a);
        a = fmaf(f0.z, w2, a); a = fmaf(f0.w, w3, a);
        acc += fmaxf(a, 0.0f);
    }
    g_aggH[(size_t)v * H + k] = acc;
}

// agg = aggH@W2 + cnt*b2 ; h += MLP(concat(h, agg))
__global__ void upd_kernel(const float* __restrict__ msgW2, const float* __restrict__ msgB2,
                           const float* __restrict__ updW1, const float* __restrict__ updB1,
                           const float* __restrict__ updW2, const float* __restrict__ updB2,
                           int r, int n) {
    __shared__ float sW2[H * H], sB2[H];
    __shared__ float sU1[64 * H], sUB1[H], sU2[H * H], sUB2[H];
    stage(sW2, msgW2 + r * H * H, H * H);
    stage(sB2, msgB2 + r * H, H);
    stage(sU1, updW1 + r * 64 * H, 64 * H);
    stage(sUB1, updB1 + r * H, H);
    stage(sU2, updW2 + r * H * H, H * H);
    stage(sUB2, updB2 + r * H, H);
    __syncthreads();

    int v = blockIdx.x * blockDim.x + threadIdx.x;
    if (v >= n) return;
    float h[H], a[H];
    const float4* hr = (const float4*)(g_h + (size_t)v * H);
    const float4* ar = (const float4*)(g_aggH + (size_t)v * H);
#pragma unroll
    for (int j = 0; j < 8; j++) {
        float4 t = hr[j];
        h[4 * j + 0] = t.x; h[4 * j + 1] = t.y; h[4 * j + 2] = t.z; h[4 * j + 3] = t.w;
        float4 u = ar[j];
        a[4 * j + 0] = u.x; a[4 * j + 1] = u.y; a[4 * j + 2] = u.z; a[4 * j + 3] = u.w;
    }
    float fc = (float)g_cnt[v];
    float agg[H];
#pragma unroll
    for (int k = 0; k < H; k++) {
        float s = fc * sB2[k];
#pragma unroll
        for (int i = 0; i < H; i++) s = fmaf(a[i], sW2[i * H + k], s);
        agg[k] = s;
    }
    float t[H];
#pragma unroll
    for (int k = 0; k < H; k++) {
        float s = sUB1[k];
#pragma unroll
        for (int i = 0; i < H; i++) s = fmaf(h[i], sU1[i * H + k], s);
#pragma unroll
        for (int i = 0; i < H; i++) s = fmaf(agg[i], sU1[(32 + i) * H + k], s);
        t[k] = fmaxf(s, 0.0f);
    }
    float o[H];
#pragma unroll
    for (int k = 0; k < H; k++) {
        float s = sUB2[k];
#pragma unroll
        for (int i = 0; i < H; i++) s = fmaf(t[i], sU2[i * H + k], s);
        o[k] = h[k] + s;
    }
    float4* hw = (float4*)(g_h + (size_t)v * H);
#pragma unroll
    for (int j = 0; j < 8; j++)
        hw[j] = make_float4(o[4 * j], o[4 * j + 1], o[4 * j + 2], o[4 * j + 3]);
}

// out = MLP(h)[:,0]
__global__ void head_kernel(float* __restrict__ out,
                            const float* __restrict__ w1, const float* __restrict__ b1,
                            const float* __restrict__ w2, const float* __restrict__ b2,
                            int n) {
    __shared__ float sW1[H * H], sB1[H], sW2[H], sB2[1];
    stage(sW1, w1, H * H);
    stage(sB1, b1, H);
    stage(sW2, w2, H);
    stage(sB2, b2, 1);
    __syncthreads();

    int v = blockIdx.x * blockDim.x + threadIdx.x;
    if (v >= n) return;
    float h[H];
    const float4* hr = (const float4*)(g_h + (size_t)v * H);
#pragma unroll
    for (int j = 0; j < 8; j++) {
        float4 t = hr[j];
        h[4 * j + 0] = t.x; h[4 * j + 1] = t.y; h[4 * j + 2] = t.z; h[4 * j + 3] = t.w;
    }
    float t1[H];
    mlp_layer<H, true>(h, t1, sW1, sB1);
    float s = sB2[0];
#pragma unroll
    for (int k = 0; k < H; k++) s = fmaf(t1[k], sW2[k], s);
    out[v] = s;
}

// ---------------- launch ----------------------------------------------------
extern "C" void kernel_launch(void* const* d_in, const int* in_sizes, int n_in,
                              void* d_out, int out_size) {
    const float*  nf   = (const float*)d_in[0];
    const int*    ew   = (const int*)d_in[1];
    const float4* ef   = (const float4*)d_in[2];
    const float* encW1 = (const float*)d_in[3];
    const float* encB1 = (const float*)d_in[4];
    const float* encW2 = (const float*)d_in[5];
    const float* encB2 = (const float*)d_in[6];
    const float* msgW1 = (const float*)d_in[7];
    const float* msgB1 = (const float*)d_in[8];
    const float* msgW2 = (const float*)d_in[9];
    const float* msgB2 = (const float*)d_in[10];
    const float* updW1 = (const float*)d_in[11];
    const float* updB1 = (const float*)d_in[12];
    const float* updW2 = (const float*)d_in[13];
    const float* updB2 = (const float*)d_in[14];
    const float* headW1 = (const float*)d_in[15];
    const float* headB1 = (const float*)d_in[16];
    const float* headW2 = (const float*)d_in[17];
    const float* headB2 = (const float*)d_in[18];

    int n  = in_sizes[0] / 16;
    int ne = in_sizes[1] / 2;

    const int NB = 128;
    int gn = (n + NB - 1) / NB;
    const int EB = 256;
    int ge = (ne + EB - 1) / EB;
    int gw = (n * 32 + 255) / 256;   // gather: warp per node, 256 thr/block

    probe_kernel<<<1, 32>>>(ew);
    enc_kernel<<<gn, NB>>>(nf, encW1, encB1, encW2, encB2, n);
    count_kernel<<<ge, EB>>>(ew, ne);
    scan_kernel<<<1, 1024>>>(n);
    scatter_kernel<<<ge, EB>>>(ew, ef, ne);
    for (int r = 0; r < 2; r++) {
        pq_kernel<<<gn, NB>>>(msgW1, r, n);
        gather_kernel<<<gw, 256>>>(msgW1, msgB1, r, n);
        upd_kernel<<<gn, NB>>>(msgW2, msgB2, updW1, updB1, updW2, updB2, r, n);
    }
    head_kernel<<<gn, NB>>>((float*)d_out, headW1, headB1, headW2, headB2, n);
}

// round 6
// speedup vs baseline: 2.9517x; 1.2911x over previous
#include <cuda_runtime.h>
#include <cuda_bf16.h>

#define NN 100000
#define NEMAX 3200000
#define H  32
#define SCAN_TILE 1024
#define MAX_PARTS 128

// ---------------- scratch (device globals; no allocation allowed) ----------
__device__ __align__(16) float g_h   [NN * H];
__device__ __align__(16) float g_p   [NN * H];
__device__ __align__(16) float g_q   [NN * H];
__device__ __align__(16) float g_aggH[NN * H];
__device__ int    g_cnt [NN];
__device__ int    g_off [NN + 1];
__device__ int    g_fill[NN];
__device__ int    g_part[MAX_PARTS];
__device__ int    g_partoff[MAX_PARTS];
__device__ int    g_csrc[NEMAX];                 // src ids in dst-sorted order
__device__ __align__(16) float g_cef[NEMAX * 4]; // edge features, dst-sorted
__device__ int    g_is64;

// cooperative copy global -> shared
__device__ __forceinline__ void stage(float* __restrict__ s,
                                      const float* __restrict__ g, int count) {
    for (int i = threadIdx.x; i < count; i += blockDim.x) s[i] = g[i];
}

__device__ __forceinline__ void load_edge(const int* __restrict__ ew, int e, int is64,
                                          int& src, int& dst) {
    if (is64) { src = ew[4 * e]; dst = ew[4 * e + 2]; }
    else      { src = ew[2 * e]; dst = ew[2 * e + 1]; }
}

template <int IN, bool RELU>
__device__ __forceinline__ void mlp_layer(const float* __restrict__ x,
                                          float* __restrict__ out,
                                          const float* __restrict__ W,
                                          const float* __restrict__ b) {
#pragma unroll
    for (int k = 0; k < H; k++) {
        float s = b[k];
#pragma unroll
        for (int i = 0; i < IN; i++) s = fmaf(x[i], W[i * H + k], s);
        out[k] = RELU ? fmaxf(s, 0.0f) : s;
    }
}

// compute p,q from register h and store (W = 64xH block of msgW1 in shared)
__device__ __forceinline__ void emit_pq(const float* __restrict__ x,
                                        const float* __restrict__ sW, int v) {
    float o[H];
#pragma unroll
    for (int k = 0; k < H; k++) {
        float s = 0.0f;
#pragma unroll
        for (int i = 0; i < H; i++) s = fmaf(x[i], sW[i * H + k], s);
        o[k] = s;
    }
    float4* pr = (float4*)(g_p + (size_t)v * H);
#pragma unroll
    for (int j = 0; j < 8; j++)
        pr[j] = make_float4(o[4 * j], o[4 * j + 1], o[4 * j + 2], o[4 * j + 3]);
#pragma unroll
    for (int k = 0; k < H; k++) {
        float s = 0.0f;
#pragma unroll
        for (int i = 0; i < H; i++) s = fmaf(x[i], sW[(32 + i) * H + k], s);
        o[k] = s;
    }
    float4* qr = (float4*)(g_q + (size_t)v * H);
#pragma unroll
    for (int j = 0; j < 8; j++)
        qr[j] = make_float4(o[4 * j], o[4 * j + 1], o[4 * j + 2], o[4 * j + 3]);
}

// ---------------- kernels ----------------------------------------------------

__global__ void probe_kernel(const int* __restrict__ ew) {
    if (threadIdx.x == 0) {
        int allzero = 1;
        for (int i = 1; i < 64; i += 2)
            if (ew[i] != 0) { allzero = 0; break; }
        g_is64 = allzero;
    }
}

// h = MLP(node_features); zero cnt; also p,q for round 0 (fused pq).
__global__ void enc_kernel(const float* __restrict__ nf,
                           const float* __restrict__ w1, const float* __restrict__ b1,
                           const float* __restrict__ w2, const float* __restrict__ b2,
                           const float* __restrict__ msgW1,
                           int n) {
    __shared__ float sW1[16 * H], sB1[H], sW2[H * H], sB2[H], sPQ[64 * H];
    stage(sW1, w1, 16 * H);
    stage(sB1, b1, H);
    stage(sW2, w2, H * H);
    stage(sB2, b2, H);
    stage(sPQ, msgW1, 64 * H);   // round 0 W1[0:64]
    __syncthreads();

    int v = blockIdx.x * blockDim.x + threadIdx.x;
    if (v >= n) return;
    float x[16];
    const float4* nr = (const float4*)(nf + (size_t)v * 16);
#pragma unroll
    for (int j = 0; j < 4; j++) {
        float4 t = nr[j];
        x[4 * j + 0] = t.x; x[4 * j + 1] = t.y; x[4 * j + 2] = t.z; x[4 * j + 3] = t.w;
    }
    float t1[H];
    mlp_layer<16, true>(x, t1, sW1, sB1);
    float t2[H];
    mlp_layer<H, false>(t1, t2, sW2, sB2);
    float4* hr = (float4*)(g_h + (size_t)v * H);
#pragma unroll
    for (int j = 0; j < 8; j++)
        hr[j] = make_float4(t2[4 * j], t2[4 * j + 1], t2[4 * j + 2], t2[4 * j + 3]);
    g_cnt[v] = 0;
    emit_pq(t2, sPQ, v);
}

__global__ void count_kernel(const int* __restrict__ ew, int ne) {
    __shared__ int sIs64;
    if (threadIdx.x == 0) sIs64 = g_is64;
    __syncthreads();
    int e = blockIdx.x * blockDim.x + threadIdx.x;
    if (e >= ne) return;
    int src, dst;
    load_edge(ew, e, sIs64, src, dst);
    atomicAdd(&g_cnt[dst], 1);
}

// ---- 3-phase parallel exclusive scan of g_cnt -> g_off/g_fill --------------
__global__ void scan_reduce_kernel(int n) {
    __shared__ int sh[256];
    int b = blockIdx.x, t = threadIdx.x;
    int base = b * SCAN_TILE;
    int s = 0;
    for (int i = t; i < SCAN_TILE; i += 256) {
        int idx = base + i;
        if (idx < n) s += g_cnt[idx];
    }
    sh[t] = s;
    __syncthreads();
    for (int o = 128; o > 0; o >>= 1) {
        if (t < o) sh[t] += sh[t + o];
        __syncthreads();
    }
    if (t == 0) g_part[b] = sh[0];
}

__global__ void scan_parts_kernel(int nb, int n) {
    __shared__ int sh[MAX_PARTS];
    int t = threadIdx.x;
    int v = (t < nb) ? g_part[t] : 0;
    sh[t] = v;
    __syncthreads();
    for (int o = 1; o < MAX_PARTS; o <<= 1) {
        int u = (t >= o) ? sh[t - o] : 0;
        __syncthreads();
        sh[t] += u;
        __syncthreads();
    }
    if (t < nb) g_partoff[t] = (t > 0) ? sh[t - 1] : 0;
    if (t == MAX_PARTS - 1) g_off[n] = sh[MAX_PARTS - 1];
}

__global__ void scan_final_kernel(int n) {
    __shared__ int sh[SCAN_TILE];
    int b = blockIdx.x, t = threadIdx.x;
    int idx = b * SCAN_TILE + t;
    int v = (idx < n) ? g_cnt[idx] : 0;
    sh[t] = v;
    __syncthreads();
    for (int o = 1; o < SCAN_TILE; o <<= 1) {
        int u = (t >= o) ? sh[t - o] : 0;
        __syncthreads();
        sh[t] += u;
        __syncthreads();
    }
    if (idx < n) {
        int ex = g_partoff[b] + sh[t] - v;
        g_off[idx] = ex;
        g_fill[idx] = ex;
    }
}

// scatter edges into dst-sorted CSR: src id + permuted edge features
__global__ void scatter_kernel(const int* __restrict__ ew,
                               const float4* __restrict__ ef, int ne) {
    __shared__ int sIs64;
    if (threadIdx.x == 0) sIs64 = g_is64;
    __syncthreads();
    int e = blockIdx.x * blockDim.x + threadIdx.x;
    if (e >= ne) return;
    int src, dst;
    load_edge(ew, e, sIs64, src, dst);
    int slot = atomicAdd(&g_fill[dst], 1);
    g_csrc[slot] = src;
    ((float4*)g_cef)[slot] = ef[e];
}

// One warp per dst node, one channel per lane. No atomics.
__global__ void gather_kernel(const float* __restrict__ msgW1,
                              const float* __restrict__ msgB1,
                              int r, int n) {
    int warp = (blockIdx.x * blockDim.x + threadIdx.x) >> 5;
    int k = threadIdx.x & 31;
    if (warp >= n) return;
    int v = warp;

    const float* Wc = msgW1 + r * 68 * H + 64 * H;
    float w0 = Wc[0 * H + k];
    float w1 = Wc[1 * H + k];
    float w2 = Wc[2 * H + k];
    float w3 = Wc[3 * H + k];
    float base = msgB1[r * H + k] + g_q[(size_t)v * H + k];

    int i0 = g_off[v];
    int i1 = g_off[v + 1];
    float acc = 0.0f;
    int i = i0;
    for (; i + 1 < i1; i += 2) {
        int s0 = g_csrc[i];
        int s1 = g_csrc[i + 1];
        float4 f0 = ((const float4*)g_cef)[i];
        float4 f1 = ((const float4*)g_cef)[i + 1];
        float pv0 = g_p[(size_t)s0 * H + k];
        float pv1 = g_p[(size_t)s1 * H + k];
        float a = pv0 + base;
        a = fmaf(f0.x, w0, a); a = fmaf(f0.y, w1, a);
        a = fmaf(f0.z, w2, a); a = fmaf(f0.w, w3, a);
        acc += fmaxf(a, 0.0f);
        float b = pv1 + base;
        b = fmaf(f1.x, w0, b); b = fmaf(f1.y, w1, b);
        b = fmaf(f1.z, w2, b); b = fmaf(f1.w, w3, b);
        acc += fmaxf(b, 0.0f);
    }
    if (i < i1) {
        int s0 = g_csrc[i];
        float4 f0 = ((const float4*)g_cef)[i];
        float pv0 = g_p[(size_t)s0 * H + k];
        float a = pv0 + base;
        a = fmaf(f0.x, w0, a); a = fmaf(f0.y, w1, a);
        a = fmaf(f0.z, w2, a); a = fmaf(f0.w, w3, a);
        acc += fmaxf(a, 0.0f);
    }
    g_aggH[(size_t)v * H + k] = acc;
}

// agg = aggH@W2 + cnt*b2 ; h += MLP(concat(h, agg)); optionally emit next p,q.
__global__ void upd_kernel(const float* __restrict__ msgW2, const float* __restrict__ msgB2,
                           const float* __restrict__ updW1, const float* __restrict__ updB1,
                           const float* __restrict__ updW2, const float* __restrict__ updB2,
                           const float* __restrict__ msgW1next,  // null-like flag via doPQ
                           int doPQ, int r, int n) {
    __shared__ float sW2[H * H], sB2[H];
    __shared__ float sU1[64 * H], sUB1[H], sU2[H * H], sUB2[H];
    __shared__ float sPQ[64 * H];
    stage(sW2, msgW2 + r * H * H, H * H);
    stage(sB2, msgB2 + r * H, H);
    stage(sU1, updW1 + r * 64 * H, 64 * H);
    stage(sUB1, updB1 + r * H, H);
    stage(sU2, updW2 + r * H * H, H * H);
    stage(sUB2, updB2 + r * H, H);
    if (doPQ) stage(sPQ, msgW1next, 64 * H);
    __syncthreads();

    int v = blockIdx.x * blockDim.x + threadIdx.x;
    if (v >= n) return;
    float h[H], a[H];
    const float4* hr = (const float4*)(g_h + (size_t)v * H);
    const float4* ar = (const float4*)(g_aggH + (size_t)v * H);
#pragma unroll
    for (int j = 0; j < 8; j++) {
        float4 t = hr[j];
        h[4 * j + 0] = t.x; h[4 * j + 1] = t.y; h[4 * j + 2] = t.z; h[4 * j + 3] = t.w;
        float4 u = ar[j];
        a[4 * j + 0] = u.x; a[4 * j + 1] = u.y; a[4 * j + 2] = u.z; a[4 * j + 3] = u.w;
    }
    float fc = (float)g_cnt[v];
    float agg[H];
#pragma unroll
    for (int k = 0; k < H; k++) {
        float s = fc * sB2[k];
#pragma unroll
        for (int i = 0; i < H; i++) s = fmaf(a[i], sW2[i * H + k], s);
        agg[k] = s;
    }
    float t[H];
#pragma unroll
    for (int k = 0; k < H; k++) {
        float s = sUB1[k];
#pragma unroll
        for (int i = 0; i < H; i++) s = fmaf(h[i], sU1[i * H + k], s);
#pragma unroll
        for (int i = 0; i < H; i++) s = fmaf(agg[i], sU1[(32 + i) * H + k], s);
        t[k] = fmaxf(s, 0.0f);
    }
    float o[H];
#pragma unroll
    for (int k = 0; k < H; k++) {
        float s = sUB2[k];
#pragma unroll
        for (int i = 0; i < H; i++) s = fmaf(t[i], sU2[i * H + k], s);
        o[k] = h[k] + s;
    }
    float4* hw = (float4*)(g_h + (size_t)v * H);
#pragma unroll
    for (int j = 0; j < 8; j++)
        hw[j] = make_float4(o[4 * j], o[4 * j + 1], o[4 * j + 2], o[4 * j + 3]);
    if (doPQ) emit_pq(o, sPQ, v);
}

// out = MLP(h)[:,0]
__global__ void head_kernel(float* __restrict__ out,
                            const float* __restrict__ w1, const float* __restrict__ b1,
                            const float* __restrict__ w2, const float* __restrict__ b2,
                            int n) {
    __shared__ float sW1[H * H], sB1[H], sW2[H], sB2[1];
    stage(sW1, w1, H * H);
    stage(sB1, b1, H);
    stage(sW2, w2, H);
    stage(sB2, b2, 1);
    __syncthreads();

    int v = blockIdx.x * blockDim.x + threadIdx.x;
    if (v >= n) return;
    float h[H];
    const float4* hr = (const float4*)(g_h + (size_t)v * H);
#pragma unroll
    for (int j = 0; j < 8; j++) {
        float4 t = hr[j];
        h[4 * j + 0] = t.x; h[4 * j + 1] = t.y; h[4 * j + 2] = t.z; h[4 * j + 3] = t.w;
    }
    float t1[H];
    mlp_layer<H, true>(h, t1, sW1, sB1);
    float s = sB2[0];
#pragma unroll
    for (int k = 0; k < H; k++) s = fmaf(t1[k], sW2[k], s);
    out[v] = s;
}

// ---------------- launch ----------------------------------------------------
extern "C" void kernel_launch(void* const* d_in, const int* in_sizes, int n_in,
                              void* d_out, int out_size) {
    const float*  nf   = (const float*)d_in[0];
    const int*    ew   = (const int*)d_in[1];
    const float4* ef   = (const float4*)d_in[2];
    const float* encW1 = (const float*)d_in[3];
    const float* encB1 = (const float*)d_in[4];
    const float* encW2 = (const float*)d_in[5];
    const float* encB2 = (const float*)d_in[6];
    const float* msgW1 = (const float*)d_in[7];
    const float* msgB1 = (const float*)d_in[8];
    const float* msgW2 = (const float*)d_in[9];
    const float* msgB2 = (const float*)d_in[10];
    const float* updW1 = (const float*)d_in[11];
    const float* updB1 = (const float*)d_in[12];
    const float* updW2 = (const float*)d_in[13];
    const float* updB2 = (const float*)d_in[14];
    const float* headW1 = (const float*)d_in[15];
    const float* headB1 = (const float*)d_in[16];
    const float* headW2 = (const float*)d_in[17];
    const float* headB2 = (const float*)d_in[18];

    int n  = in_sizes[0] / 16;
    int ne = in_sizes[1] / 2;

    const int NB = 128;
    int gn = (n + NB - 1) / NB;
    const int EB = 256;
    int ge = (ne + EB - 1) / EB;
    int gw = (n * 32 + 255) / 256;
    int nb = (n + SCAN_TILE - 1) / SCAN_TILE;

    probe_kernel<<<1, 32>>>(ew);
    enc_kernel<<<gn, NB>>>(nf, encW1, encB1, encW2, encB2, msgW1, n);
    count_kernel<<<ge, EB>>>(ew, ne);
    scan_reduce_kernel<<<nb, 256>>>(n);
    scan_parts_kernel<<<1, MAX_PARTS>>>(nb, n);
    scan_final_kernel<<<nb, SCAN_TILE>>>(n);
    scatter_kernel<<<ge, EB>>>(ew, ef, ne);
    for (int r = 0; r < 2; r++) {
        gather_kernel<<<gw, 256>>>(msgW1, msgB1, r, n);
        upd_kernel<<<gn, NB>>>(msgW2, msgB2, updW1, updB1, updW2, updB2,
                               msgW1 + 68 * H, (r == 0) ? 1 : 0, r, n);
    }
    head_kernel<<<gn, NB>>>((float*)d_out, headW1, headB1, headW2, headB2, n);
}

// round 7
// speedup vs baseline: 3.1264x; 1.0592x over previous
#include <cuda_runtime.h>
#include <cuda_bf16.h>

#define NN 100000
#define NEMAX 3200000
#define H  32
#define SCAN_TILE 1024
#define MAX_PARTS 128

// ---------------- scratch (device globals; no allocation allowed) ----------
__device__ __align__(16) float g_h   [NN * H];
__device__ __align__(16) float g_p   [NN * H];
__device__ __align__(16) float g_q   [NN * H];
__device__ __align__(16) float g_aggH[NN * H];
__device__ int    g_cnt [NN];
__device__ int    g_off [NN + 1];
__device__ int    g_fill[NN];
__device__ int    g_part[MAX_PARTS];
__device__ int    g_partoff[MAX_PARTS];
__device__ int    g_csrc[NEMAX];                 // src ids in dst-sorted order
__device__ __align__(16) float g_cef[NEMAX * 4]; // edge features, dst-sorted
__device__ int    g_is64;

// cooperative copy global -> shared
__device__ __forceinline__ void stage(float* __restrict__ s,
                                      const float* __restrict__ g, int count) {
    for (int i = threadIdx.x; i < count; i += blockDim.x) s[i] = g[i];
}

__device__ __forceinline__ void load_edge_vec(const int* __restrict__ ew, int e, int is64,
                                              int& src, int& dst) {
    if (is64) { int4 t = ((const int4*)ew)[e]; src = t.x; dst = t.z; }
    else      { int2 t = ((const int2*)ew)[e]; src = t.x; dst = t.y; }
}

template <int IN, bool RELU>
__device__ __forceinline__ void mlp_layer(const float* __restrict__ x,
                                          float* __restrict__ out,
                                          const float* __restrict__ W,
                                          const float* __restrict__ b) {
#pragma unroll
    for (int k = 0; k < H; k++) {
        float s = b[k];
#pragma unroll
        for (int i = 0; i < IN; i++) s = fmaf(x[i], W[i * H + k], s);
        out[k] = RELU ? fmaxf(s, 0.0f) : s;
    }
}

// compute p,q from register h and store (W = 64xH block of msgW1 in shared)
__device__ __forceinline__ void emit_pq(const float* __restrict__ x,
                                        const float* __restrict__ sW, int v) {
    float o[H];
#pragma unroll
    for (int k = 0; k < H; k++) {
        float s = 0.0f;
#pragma unroll
        for (int i = 0; i < H; i++) s = fmaf(x[i], sW[i * H + k], s);
        o[k] = s;
    }
    float4* pr = (float4*)(g_p + (size_t)v * H);
#pragma unroll
    for (int j = 0; j < 8; j++)
        pr[j] = make_float4(o[4 * j], o[4 * j + 1], o[4 * j + 2], o[4 * j + 3]);
#pragma unroll
    for (int k = 0; k < H; k++) {
        float s = 0.0f;
#pragma unroll
        for (int i = 0; i < H; i++) s = fmaf(x[i], sW[(32 + i) * H + k], s);
        o[k] = s;
    }
    float4* qr = (float4*)(g_q + (size_t)v * H);
#pragma unroll
    for (int j = 0; j < 8; j++)
        qr[j] = make_float4(o[4 * j], o[4 * j + 1], o[4 * j + 2], o[4 * j + 3]);
}

// ---------------- kernels ----------------------------------------------------

__global__ void probe_kernel(const int* __restrict__ ew) {
    if (threadIdx.x == 0) {
        int allzero = 1;
        for (int i = 1; i < 64; i += 2)
            if (ew[i] != 0) { allzero = 0; break; }
        g_is64 = allzero;
    }
}

// h = MLP(node_features); zero cnt; also p,q for round 0 (fused pq).
__global__ void enc_kernel(const float* __restrict__ nf,
                           const float* __restrict__ w1, const float* __restrict__ b1,
                           const float* __restrict__ w2, const float* __restrict__ b2,
                           const float* __restrict__ msgW1,
                           int n) {
    __shared__ float sW1[16 * H], sB1[H], sW2[H * H], sB2[H], sPQ[64 * H];
    stage(sW1, w1, 16 * H);
    stage(sB1, b1, H);
    stage(sW2, w2, H * H);
    stage(sB2, b2, H);
    stage(sPQ, msgW1, 64 * H);   // round 0 W1[0:64]
    __syncthreads();

    int v = blockIdx.x * blockDim.x + threadIdx.x;
    if (v >= n) return;
    float x[16];
    const float4* nr = (const float4*)(nf + (size_t)v * 16);
#pragma unroll
    for (int j = 0; j < 4; j++) {
        float4 t = nr[j];
        x[4 * j + 0] = t.x; x[4 * j + 1] = t.y; x[4 * j + 2] = t.z; x[4 * j + 3] = t.w;
    }
    float t1[H];
    mlp_layer<16, true>(x, t1, sW1, sB1);
    float t2[H];
    mlp_layer<H, false>(t1, t2, sW2, sB2);
    float4* hr = (float4*)(g_h + (size_t)v * H);
#pragma unroll
    for (int j = 0; j < 8; j++)
        hr[j] = make_float4(t2[4 * j], t2[4 * j + 1], t2[4 * j + 2], t2[4 * j + 3]);
    g_cnt[v] = 0;
    emit_pq(t2, sPQ, v);
}

__global__ void count_kernel(const int* __restrict__ ew, int ne) {
    __shared__ int sIs64;
    if (threadIdx.x == 0) sIs64 = g_is64;
    __syncthreads();
    int e = blockIdx.x * blockDim.x + threadIdx.x;
    if (e >= ne) return;
    int src, dst;
    load_edge_vec(ew, e, sIs64, src, dst);
    atomicAdd(&g_cnt[dst], 1);
}

// ---- 3-phase parallel exclusive scan of g_cnt -> g_off/g_fill --------------
__global__ void scan_reduce_kernel(int n) {
    __shared__ int sh[256];
    int b = blockIdx.x, t = threadIdx.x;
    int base = b * SCAN_TILE;
    int s = 0;
    for (int i = t; i < SCAN_TILE; i += 256) {
        int idx = base + i;
        if (idx < n) s += g_cnt[idx];
    }
    sh[t] = s;
    __syncthreads();
    for (int o = 128; o > 0; o >>= 1) {
        if (t < o) sh[t] += sh[t + o];
        __syncthreads();
    }
    if (t == 0) g_part[b] = sh[0];
}

__global__ void scan_parts_kernel(int nb, int n) {
    __shared__ int sh[MAX_PARTS];
    int t = threadIdx.x;
    int v = (t < nb) ? g_part[t] : 0;
    sh[t] = v;
    __syncthreads();
    for (int o = 1; o < MAX_PARTS; o <<= 1) {
        int u = (t >= o) ? sh[t - o] : 0;
        __syncthreads();
        sh[t] += u;
        __syncthreads();
    }
    if (t < nb) g_partoff[t] = (t > 0) ? sh[t - 1] : 0;
    if (t == MAX_PARTS - 1) g_off[n] = sh[MAX_PARTS - 1];
}

__global__ void scan_final_kernel(int n) {
    __shared__ int sh[SCAN_TILE];
    int b = blockIdx.x, t = threadIdx.x;
    int idx = b * SCAN_TILE + t;
    int v = (idx < n) ? g_cnt[idx] : 0;
    sh[t] = v;
    __syncthreads();
    for (int o = 1; o < SCAN_TILE; o <<= 1) {
        int u = (t >= o) ? sh[t - o] : 0;
        __syncthreads();
        sh[t] += u;
        __syncthreads();
    }
    if (idx < n) {
        int ex = g_partoff[b] + sh[t] - v;
        g_off[idx] = ex;
        g_fill[idx] = ex;
    }
}

// scatter edges into dst-sorted CSR: src id + permuted edge features
__global__ void scatter_kernel(const int* __restrict__ ew,
                               const float4* __restrict__ ef, int ne) {
    __shared__ int sIs64;
    if (threadIdx.x == 0) sIs64 = g_is64;
    __syncthreads();
    int e = blockIdx.x * blockDim.x + threadIdx.x;
    if (e >= ne) return;
    int src, dst;
    load_edge_vec(ew, e, sIs64, src, dst);
    int slot = atomicAdd(&g_fill[dst], 1);
    g_csrc[slot] = src;
    ((float4*)g_cef)[slot] = ef[e];
}

// One warp per dst node, channel per lane. Chunked smem staging: each lane
// loads one edge's (src, ef) coalesced; inner loop reads via LDS broadcast.
__global__ void gather_kernel(const float* __restrict__ msgW1,
                              const float* __restrict__ msgB1,
                              int r, int n) {
    __shared__ int   sSrc[8][32];
    __shared__ float4 sEf[8][32];

    int warp = (blockIdx.x * blockDim.x + threadIdx.x) >> 5;
    int w = (threadIdx.x >> 5) & 7;
    int k = threadIdx.x & 31;
    if (warp >= n) return;
    int v = warp;

    const float* Wc = msgW1 + r * 68 * H + 64 * H;
    float w0 = Wc[0 * H + k];
    float w1 = Wc[1 * H + k];
    float w2 = Wc[2 * H + k];
    float w3 = Wc[3 * H + k];
    float base = msgB1[r * H + k] + g_q[(size_t)v * H + k];

    int i0 = g_off[v];
    int i1 = g_off[v + 1];
    float acc = 0.0f;

    for (int cbase = i0; cbase < i1; cbase += 32) {
        int cnt = i1 - cbase;
        if (cnt > 32) cnt = 32;
        int idx = cbase + k;
        if (k < cnt) {
            sSrc[w][k] = g_csrc[idx];
            sEf[w][k]  = ((const float4*)g_cef)[idx];
        }
        __syncwarp();
#pragma unroll 4
        for (int j = 0; j < cnt; j++) {
            int s = sSrc[w][j];
            float4 f = sEf[w][j];
            float pv = g_p[(size_t)s * H + k];
            float a = pv + base;
            a = fmaf(f.x, w0, a); a = fmaf(f.y, w1, a);
            a = fmaf(f.z, w2, a); a = fmaf(f.w, w3, a);
            acc += fmaxf(a, 0.0f);
        }
        __syncwarp();
    }
    g_aggH[(size_t)v * H + k] = acc;
}

// agg = aggH@W2 + cnt*b2 ; h += MLP(concat(h, agg)).
// doPQ: emit p,q for next round. doHead: compute head MLP, write out, skip h store.
__global__ void upd_kernel(const float* __restrict__ msgW2, const float* __restrict__ msgB2,
                           const float* __restrict__ updW1, const float* __restrict__ updB1,
                           const float* __restrict__ updW2, const float* __restrict__ updB2,
                           const float* __restrict__ msgW1next,
                           const float* __restrict__ hw1, const float* __restrict__ hb1,
                           const float* __restrict__ hw2, const float* __restrict__ hb2,
                           float* __restrict__ out,
                           int doPQ, int doHead, int r, int n) {
    __shared__ float sW2[H * H], sB2[H];
    __shared__ float sU1[64 * H], sUB1[H], sU2[H * H], sUB2[H];
    __shared__ float sPQ[64 * H];   // reused for head W1 when doHead
    __shared__ float sHW2[H], sHB1[H], sHB2[1];
    stage(sW2, msgW2 + r * H * H, H * H);
    stage(sB2, msgB2 + r * H, H);
    stage(sU1, updW1 + r * 64 * H, 64 * H);
    stage(sUB1, updB1 + r * H, H);
    stage(sU2, updW2 + r * H * H, H * H);
    stage(sUB2, updB2 + r * H, H);
    if (doPQ) stage(sPQ, msgW1next, 64 * H);
    if (doHead) {
        stage(sPQ, hw1, H * H);
        stage(sHW2, hw2, H);
        stage(sHB1, hb1, H);
        stage(sHB2, hb2, 1);
    }
    __syncthreads();

    int v = blockIdx.x * blockDim.x + threadIdx.x;
    if (v >= n) return;
    float h[H], a[H];
    const float4* hr = (const float4*)(g_h + (size_t)v * H);
    const float4* ar = (const float4*)(g_aggH + (size_t)v * H);
#pragma unroll
    for (int j = 0; j < 8; j++) {
        float4 t = hr[j];
        h[4 * j + 0] = t.x; h[4 * j + 1] = t.y; h[4 * j + 2] = t.z; h[4 * j + 3] = t.w;
        float4 u = ar[j];
        a[4 * j + 0] = u.x; a[4 * j + 1] = u.y; a[4 * j + 2] = u.z; a[4 * j + 3] = u.w;
    }
    float fc = (float)g_cnt[v];
    float agg[H];
#pragma unroll
    for (int k = 0; k < H; k++) {
        float s = fc * sB2[k];
#pragma unroll
        for (int i = 0; i < H; i++) s = fmaf(a[i], sW2[i * H + k], s);
        agg[k] = s;
    }
    float t[H];
#pragma unroll
    for (int k = 0; k < H; k++) {
        float s = sUB1[k];
#pragma unroll
        for (int i = 0; i < H; i++) s = fmaf(h[i], sU1[i * H + k], s);
#pragma unroll
        for (int i = 0; i < H; i++) s = fmaf(agg[i], sU1[(32 + i) * H + k], s);
        t[k] = fmaxf(s, 0.0f);
    }
    float o[H];
#pragma unroll
    for (int k = 0; k < H; k++) {
        float s = sUB2[k];
#pragma unroll
        for (int i = 0; i < H; i++) s = fmaf(t[i], sU2[i * H + k], s);
        o[k] = h[k] + s;
    }
    if (doHead) {
        // out[v] = (relu(o @ HW1 + HB1)) @ HW2 + HB2
        float s2 = sHB2[0];
#pragma unroll
        for (int k = 0; k < H; k++) {
            float s = sHB1[k];
#pragma unroll
            for (int i = 0; i < H; i++) s = fmaf(o[i], sPQ[i * H + k], s);
            s2 = fmaf(fmaxf(s, 0.0f), sHW2[k], s2);
        }
        out[v] = s2;
        return;
    }
    float4* hwp = (float4*)(g_h + (size_t)v * H);
#pragma unroll
    for (int j = 0; j < 8; j++)
        hwp[j] = make_float4(o[4 * j], o[4 * j + 1], o[4 * j + 2], o[4 * j + 3]);
    if (doPQ) emit_pq(o, sPQ, v);
}

// ---------------- launch ----------------------------------------------------
extern "C" void kernel_launch(void* const* d_in, const int* in_sizes, int n_in,
                              void* d_out, int out_size) {
    const float*  nf   = (const float*)d_in[0];
    const int*    ew   = (const int*)d_in[1];
    const float4* ef   = (const float4*)d_in[2];
    const float* encW1 = (const float*)d_in[3];
    const float* encB1 = (const float*)d_in[4];
    const float* encW2 = (const float*)d_in[5];
    const float* encB2 = (const float*)d_in[6];
    const float* msgW1 = (const float*)d_in[7];
    const float* msgB1 = (const float*)d_in[8];
    const float* msgW2 = (const float*)d_in[9];
    const float* msgB2 = (const float*)d_in[10];
    const float* updW1 = (const float*)d_in[11];
    const float* updB1 = (const float*)d_in[12];
    const float* updW2 = (const float*)d_in[13];
    const float* updB2 = (const float*)d_in[14];
    const float* headW1 = (const float*)d_in[15];
    const float* headB1 = (const float*)d_in[16];
    const float* headW2 = (const float*)d_in[17];
    const float* headB2 = (const float*)d_in[18];

    int n  = in_sizes[0] / 16;
    int ne = in_sizes[1] / 2;

    const int NB = 128;
    int gn = (n + NB - 1) / NB;
    const int EB = 256;
    int ge = (ne + EB - 1) / EB;
    int gw = (n * 32 + 255) / 256;
    int nb = (n + SCAN_TILE - 1) / SCAN_TILE;

    probe_kernel<<<1, 32>>>(ew);
    enc_kernel<<<gn, NB>>>(nf, encW1, encB1, encW2, encB2, msgW1, n);
    count_kernel<<<ge, EB>>>(ew, ne);
    scan_reduce_kernel<<<nb, 256>>>(n);
    scan_parts_kernel<<<1, MAX_PARTS>>>(nb, n);
    scan_final_kernel<<<nb, SCAN_TILE>>>(n);
    scatter_kernel<<<ge, EB>>>(ew, ef, ne);
    for (int r = 0; r < 2; r++) {
        gather_kernel<<<gw, 256>>>(msgW1, msgB1, r, n);
        upd_kernel<<<gn, NB>>>(msgW2, msgB2, updW1, updB1, updW2, updB2,
                               msgW1 + 68 * H,
                               headW1, headB1, headW2, headB2, (float*)d_out,
                               (r == 0) ? 1 : 0, (r == 1) ? 1 : 0, r, n);
    }
}